// round 2
// baseline (speedup 1.0000x reference)
#include <cuda_runtime.h>
#include <math.h>

#define Bx 512
#define Tt 256
#define Ii 128
#define Hh 512
#define G3 1536

// ---------------- scratch (device globals; no allocation allowed) ----------------
__device__ float g_xg[(size_t)Tt * (size_t)Bx * (size_t)G3]; // [T][B][3H], 805 MB
__device__ float g_h[2][Bx * Hh];                            // ping-pong hidden state

// ---------------- init: zero h0 (every launch, deterministic) --------------------
__global__ void init_kernel() {
    int i = blockIdx.x * 256 + threadIdx.x;
    if (i < Bx * Hh) g_h[0][i] = 0.0f;
}

// ---------------- kernel 1: xg[t][b][g] = x[b,t,:] @ W_ih[g,:] + bias ------------
// bias = b_ih[g] + b_hh[g] for r/z gates (g < 2H); b_ih[g] only for n gate
// (b_hh of the n gate sits INSIDE r*hn, folded into the step kernel instead).
__global__ __launch_bounds__(256) void xg_kernel(
    const float* __restrict__ x, const float* __restrict__ Wih,
    const float* __restrict__ bih, const float* __restrict__ bhh)
{
    __shared__ float As[64][68];
    __shared__ float Bs[64][68];
    const int bt0 = blockIdx.x * 64;   // row tile over B*T = 131072
    const int n0  = blockIdx.y * 64;   // col tile over 3H = 1536
    const int tid = threadIdx.x;
    const int tx = tid & 15, ty = tid >> 4;

    float acc[4][4];
#pragma unroll
    for (int i = 0; i < 4; ++i)
#pragma unroll
        for (int j = 0; j < 4; ++j) acc[i][j] = 0.0f;

    for (int kc = 0; kc < 2; ++kc) {
        const int kb = kc * 64;
#pragma unroll
        for (int i = 0; i < 4; ++i) {
            int q = tid + 256 * i;
            int r = q >> 4, c4 = q & 15;
            float4 v = *(const float4*)(x + (size_t)(bt0 + r) * Ii + kb + c4 * 4);
            As[c4 * 4 + 0][r] = v.x; As[c4 * 4 + 1][r] = v.y;
            As[c4 * 4 + 2][r] = v.z; As[c4 * 4 + 3][r] = v.w;
        }
#pragma unroll
        for (int i = 0; i < 4; ++i) {
            int q = tid + 256 * i;
            int r = q >> 4, c4 = q & 15;
            float4 v = *(const float4*)(Wih + (size_t)(n0 + r) * Ii + kb + c4 * 4);
            Bs[c4 * 4 + 0][r] = v.x; Bs[c4 * 4 + 1][r] = v.y;
            Bs[c4 * 4 + 2][r] = v.z; Bs[c4 * 4 + 3][r] = v.w;
        }
        __syncthreads();
#pragma unroll 16
        for (int k = 0; k < 64; ++k) {
            float4 a4 = *(const float4*)&As[k][ty * 4];
            float4 b4 = *(const float4*)&Bs[k][tx * 4];
            float av[4] = {a4.x, a4.y, a4.z, a4.w};
            float bv[4] = {b4.x, b4.y, b4.z, b4.w};
#pragma unroll
            for (int i = 0; i < 4; ++i)
#pragma unroll
                for (int j = 0; j < 4; ++j) acc[i][j] += av[i] * bv[j];
        }
        __syncthreads();
    }

#pragma unroll
    for (int i = 0; i < 4; ++i) {
        int bt = bt0 + ty * 4 + i;
        int b = bt / Tt, t = bt % Tt;       // x rows are [B][T]
        float* dst = g_xg + ((size_t)t * Bx + b) * G3 + n0 + tx * 4;
#pragma unroll
        for (int j = 0; j < 4; ++j) {
            int g = n0 + tx * 4 + j;
            float bias = bih[g] + (g < 2 * Hh ? bhh[g] : 0.0f);
            dst[j] = acc[i][j] + bias;
        }
    }
}

// ---------------- kernel 2: one GRU timestep ------------------------------------
// hg = h_t @ W_hh^T for a 64-batch x 96-gate tile (r,z,n x 32 j), then fused
// gate nonlinearity + h update. One launch per timestep; launch boundary gives
// cross-block memory ordering (no grid barrier, no co-residency assumption).
__global__ __launch_bounds__(256) void gru_step_kernel(
    int t, const float* __restrict__ Whh, const float* __restrict__ bhh)
{
    __shared__ float As[64][68];    // h tile, transposed [k][b]
    __shared__ float Ws[64][100];   // W tile [k][p]; reused as C[b][p] in epilogue
    const int tid = threadIdx.x;
    const int tx = tid & 15, ty = tid >> 4;
    const int btile = blockIdx.x >> 4, jtile = blockIdx.x & 15;
    const int b0 = btile * 64, j0 = jtile * 32;

    const float* hin = g_h[t & 1];
    float* hout = g_h[(t + 1) & 1];

    float acc[4][6];
#pragma unroll
    for (int i = 0; i < 4; ++i)
#pragma unroll
        for (int j = 0; j < 6; ++j) {
            int p = tx * 6 + j;
            // n-gate h-side keeps b_hh (it sits INSIDE r*hn)
            acc[i][j] = (p >= 64) ? bhh[2 * Hh + j0 + (p - 64)] : 0.0f;
        }

    for (int kc = 0; kc < 8; ++kc) {
        const int kb = kc * 64;
        // A tile: 64 h-rows x 64 k-cols, stored transposed [k][b]
#pragma unroll
        for (int i = 0; i < 4; ++i) {
            int q = tid + 256 * i;
            int r = q >> 4, c4 = q & 15;
            float4 v = *(const float4*)(hin + (size_t)(b0 + r) * Hh + kb + c4 * 4);
            As[c4 * 4 + 0][r] = v.x; As[c4 * 4 + 1][r] = v.y;
            As[c4 * 4 + 2][r] = v.z; As[c4 * 4 + 3][r] = v.w;
        }
        // W tile: 96 p-rows; p -> gate row g = j0 + (p%32) + 512*(p/32)
#pragma unroll
        for (int i = 0; i < 6; ++i) {
            int q = tid + 256 * i;
            int p = q >> 4, c4 = q & 15;
            int g = j0 + (p & 31) + ((p >> 5) << 9);
            float4 v = *(const float4*)(Whh + (size_t)g * Hh + kb + c4 * 4);
            Ws[c4 * 4 + 0][p] = v.x; Ws[c4 * 4 + 1][p] = v.y;
            Ws[c4 * 4 + 2][p] = v.z; Ws[c4 * 4 + 3][p] = v.w;
        }
        __syncthreads();
#pragma unroll 16
        for (int k = 0; k < 64; ++k) {
            float4 a4 = *(const float4*)&As[k][ty * 4];
            float av[4] = {a4.x, a4.y, a4.z, a4.w};
            float wv[6];
#pragma unroll
            for (int j = 0; j < 6; ++j) wv[j] = Ws[k][tx * 6 + j];
#pragma unroll
            for (int i = 0; i < 4; ++i)
#pragma unroll
                for (int j = 0; j < 6; ++j) acc[i][j] += av[i] * wv[j];
        }
        __syncthreads();
    }

    // stage C = hg into smem (reuse Ws) so each thread can gather (r,z,n) per j
#pragma unroll
    for (int i = 0; i < 4; ++i)
#pragma unroll
        for (int j = 0; j < 6; ++j)
            Ws[ty * 4 + i][tx * 6 + j] = acc[i][j];
    __syncthreads();

    const float* xg_t = g_xg + (size_t)t * Bx * G3;
#pragma unroll
    for (int s = 0; s < 8; ++s) {
        int e = tid + 256 * s;          // 64 b x 32 j = 2048 updates / block
        int lb = e >> 5, jj = e & 31;
        int gb = b0 + lb, gj = j0 + jj;
        const float* xp = xg_t + (size_t)gb * G3 + gj;
        float xr = xp[0], xz = xp[Hh], xn = xp[2 * Hh];
        float hr = Ws[lb][jj], hz = Ws[lb][32 + jj], hn = Ws[lb][64 + jj];
        float r = 1.0f / (1.0f + expf(-(xr + hr)));
        float z = 1.0f / (1.0f + expf(-(xz + hz)));
        float n = tanhf(xn + r * hn);
        float hprev = hin[(size_t)gb * Hh + gj];
        hout[(size_t)gb * Hh + gj] = (1.0f - z) * n + z * hprev;
    }
}

// ---------------- kernel 3: out[b] = h_T[b,:] @ W_lin + b_lin -------------------
__global__ void out_kernel(const float* __restrict__ Wlin,
                           const float* __restrict__ blin,
                           float* __restrict__ out)
{
    int w = (blockIdx.x * blockDim.x + threadIdx.x) >> 5; // one warp per batch row
    int lane = threadIdx.x & 31;
    if (w >= Bx) return;
    const float* h = g_h[0] + (size_t)w * Hh;   // T=256 even -> final state in buf 0
    float s = 0.0f;
#pragma unroll
    for (int i = 0; i < Hh / 32; ++i) s += h[lane + 32 * i] * Wlin[lane + 32 * i];
#pragma unroll
    for (int o = 16; o; o >>= 1) s += __shfl_xor_sync(0xffffffffu, s, o);
    if (lane == 0) out[w] = s + blin[0];
}

// ---------------- launch ---------------------------------------------------------
extern "C" void kernel_launch(void* const* d_in, const int* in_sizes, int n_in,
                              void* d_out, int out_size)
{
    const float* x    = (const float*)d_in[0];
    const float* Wih  = (const float*)d_in[1];
    const float* Whh  = (const float*)d_in[2];
    const float* bih  = (const float*)d_in[3];
    const float* bhh  = (const float*)d_in[4];
    const float* Wlin = (const float*)d_in[5];
    const float* blin = (const float*)d_in[6];
    float* out = (float*)d_out;

    init_kernel<<<(Bx * Hh + 255) / 256, 256>>>();
    dim3 gx((Bx * Tt) / 64, G3 / 64);
    xg_kernel<<<gx, 256>>>(x, Wih, bih, bhh);
    for (int t = 0; t < Tt; ++t)
        gru_step_kernel<<<128, 256>>>(t, Whh, bhh);
    out_kernel<<<(Bx * 32) / 256, 256>>>(Wlin, blin, out);
}

// round 3
// speedup vs baseline: 1.6001x; 1.6001x over previous
#include <cuda_runtime.h>
#include <cuda_bf16.h>
#include <math.h>
#include <stdint.h>

#define Bx 512
#define Tt 256
#define Ii 128
#define Hh 512
#define G3 1536

// ---------------- scratch (device globals; no allocation allowed) ----------------
__device__ float g_xg[(size_t)Tt * (size_t)Bx * (size_t)G3]; // [T][B][3H] fp32
__device__ float g_h[2][Bx * Hh];                            // fp32 hidden, ping-pong
__device__ __nv_bfloat16 g_hhi[2][Bx * Hh];                  // h split-bf16 hi (perm-k)
__device__ __nv_bfloat16 g_hlo[2][Bx * Hh];                  // h split-bf16 lo (perm-k)
__device__ __nv_bfloat16 g_Whi[(size_t)G3 * Hh];             // W_hh bf16 hi (perm-k)
__device__ __nv_bfloat16 g_Wlo[(size_t)G3 * Hh];             // W_hh bf16 lo (perm-k)

// permutation within each 16-k block so mma fragment (k, k+1, k+8, k+9) is one LDS.64
__device__ __forceinline__ int kperm(int k) {
    return ((k & 7) >> 1) * 4 + (k & 1) + (((k >> 3) & 1) << 1);
}

// ---------------- init: zero h0 (fp32 + bf16 hi/lo), every launch ---------------
__global__ void init_kernel() {
    int i = blockIdx.x * 256 + threadIdx.x;
    if (i < Bx * Hh) {
        g_h[0][i] = 0.0f;
        g_hhi[0][i] = __float2bfloat16(0.0f);
        g_hlo[0][i] = __float2bfloat16(0.0f);
    }
}

// ---------------- W_hh -> split bf16, permuted-k layout (once per launch) --------
__global__ void wconv_kernel(const float* __restrict__ Whh) {
    int idx = blockIdx.x * 256 + threadIdx.x;
    if (idx >= G3 * Hh) return;
    int row = idx >> 9, k = idx & 511;
    float w = Whh[idx];
    __nv_bfloat16 hi = __float2bfloat16(w);
    float lo = w - __bfloat162float(hi);
    int kk = (k & ~15) + kperm(k & 15);
    g_Whi[(size_t)row * Hh + kk] = hi;
    g_Wlo[(size_t)row * Hh + kk] = __float2bfloat16(lo);
}

// ---------------- kernel 1: xg[t][b][g] = x[b,t,:] @ W_ih[g,:] + bias ------------
// bias = b_ih + b_hh for r/z gates; b_ih only for n gate (b_hh_n sits inside r*hn).
__global__ __launch_bounds__(256) void xg_kernel(
    const float* __restrict__ x, const float* __restrict__ Wih,
    const float* __restrict__ bih, const float* __restrict__ bhh)
{
    __shared__ float As[64][68];
    __shared__ float Bs[64][68];
    const int bt0 = blockIdx.x * 64;
    const int n0  = blockIdx.y * 64;
    const int tid = threadIdx.x;
    const int tx = tid & 15, ty = tid >> 4;

    float acc[4][4];
#pragma unroll
    for (int i = 0; i < 4; ++i)
#pragma unroll
        for (int j = 0; j < 4; ++j) acc[i][j] = 0.0f;

    for (int kc = 0; kc < 2; ++kc) {
        const int kb = kc * 64;
#pragma unroll
        for (int i = 0; i < 4; ++i) {
            int q = tid + 256 * i;
            int r = q >> 4, c4 = q & 15;
            float4 v = *(const float4*)(x + (size_t)(bt0 + r) * Ii + kb + c4 * 4);
            As[c4 * 4 + 0][r] = v.x; As[c4 * 4 + 1][r] = v.y;
            As[c4 * 4 + 2][r] = v.z; As[c4 * 4 + 3][r] = v.w;
        }
#pragma unroll
        for (int i = 0; i < 4; ++i) {
            int q = tid + 256 * i;
            int r = q >> 4, c4 = q & 15;
            float4 v = *(const float4*)(Wih + (size_t)(n0 + r) * Ii + kb + c4 * 4);
            Bs[c4 * 4 + 0][r] = v.x; Bs[c4 * 4 + 1][r] = v.y;
            Bs[c4 * 4 + 2][r] = v.z; Bs[c4 * 4 + 3][r] = v.w;
        }
        __syncthreads();
#pragma unroll 16
        for (int k = 0; k < 64; ++k) {
            float4 a4 = *(const float4*)&As[k][ty * 4];
            float4 b4 = *(const float4*)&Bs[k][tx * 4];
            float av[4] = {a4.x, a4.y, a4.z, a4.w};
            float bv[4] = {b4.x, b4.y, b4.z, b4.w};
#pragma unroll
            for (int i = 0; i < 4; ++i)
#pragma unroll
                for (int j = 0; j < 4; ++j) acc[i][j] += av[i] * bv[j];
        }
        __syncthreads();
    }

#pragma unroll
    for (int i = 0; i < 4; ++i) {
        int bt = bt0 + ty * 4 + i;
        int b = bt / Tt, t = bt % Tt;       // x rows are [B][T]
        float* dst = g_xg + ((size_t)t * Bx + b) * G3 + n0 + tx * 4;
#pragma unroll
        for (int j = 0; j < 4; ++j) {
            int g = n0 + tx * 4 + j;
            float bias = bih[g] + (g < 2 * Hh ? bhh[g] : 0.0f);
            dst[j] = acc[i][j] + bias;
        }
    }
}

// ---------------- bf16 mma.sync helper ------------------------------------------
__device__ __forceinline__ void mma_bf16(float* c,
    uint32_t a0, uint32_t a1, uint32_t a2, uint32_t a3,
    uint32_t b0, uint32_t b1)
{
    asm volatile(
        "mma.sync.aligned.m16n8k16.row.col.f32.bf16.bf16.f32 "
        "{%0,%1,%2,%3},{%4,%5,%6,%7},{%8,%9},{%0,%1,%2,%3};"
        : "+f"(c[0]), "+f"(c[1]), "+f"(c[2]), "+f"(c[3])
        : "r"(a0), "r"(a1), "r"(a2), "r"(a3), "r"(b0), "r"(b1));
}

// smem row strides (bf16 units): 80 -> 160B rows, conflict-free LDS.64 fragments
#define AST 80
#define BST 80
// dynamic smem partition (bf16 units)
#define OFF_AHI 0
#define OFF_ALO (64 * AST)
#define OFF_BHI (2 * 64 * AST)
#define OFF_BLO (2 * 64 * AST + 96 * BST)
#define SMEM_BYTES ((2 * 64 * AST + 2 * 96 * BST) * 2)

// ---------------- kernel 2: one GRU timestep (tensor-core, split-bf16) -----------
// hg = h @ W_hh^T for a 64-batch x (3 gates x 32 j) tile. Each warp owns a
// 16b x 16j tile across ALL 3 gates -> gate epilogue fully in registers.
__global__ __launch_bounds__(256) void gru_step_kernel(
    int t, const float* __restrict__ bhh)
{
    extern __shared__ __nv_bfloat16 sm[];
    __nv_bfloat16* As_hi = sm + OFF_AHI;
    __nv_bfloat16* As_lo = sm + OFF_ALO;
    __nv_bfloat16* Bs_hi = sm + OFF_BHI;
    __nv_bfloat16* Bs_lo = sm + OFF_BLO;

    const int tid  = threadIdx.x;
    const int lane = tid & 31;
    const int w    = tid >> 5;          // 8 warps
    const int mt   = w >> 1;            // 4 m-tiles of 16 batch rows
    const int jp   = w & 1;             // 2 j-halves of 16 cols
    const int qrow = lane >> 2;         // 0..7
    const int qcol = lane & 3;          // 0..3

    const int btile = blockIdx.x >> 4, jtile = blockIdx.x & 15;
    const int b0 = btile * 64, j0 = jtile * 32;

    const __nv_bfloat16* hhi_in = g_hhi[t & 1];
    const __nv_bfloat16* hlo_in = g_hlo[t & 1];

    float acc[3][2][4];                 // [gate][n-tile][c-regs]
#pragma unroll
    for (int g = 0; g < 3; ++g)
#pragma unroll
        for (int nt = 0; nt < 2; ++nt)
#pragma unroll
            for (int e = 0; e < 4; ++e) acc[g][nt][e] = 0.0f;

    const int ar0 = mt * 16 + qrow;
    const int ar8 = ar0 + 8;

    for (int ch = 0; ch < 8; ++ch) {
        const int kb = ch * 64;
        __syncthreads();   // previous chunk fully consumed
        // stage A: 64 rows x 64 k (permuted layout -> 128B contiguous per row)
#pragma unroll
        for (int i = 0; i < 2; ++i) {
            int q = tid + 256 * i;
            int r = q >> 3, pos = q & 7;
            size_t goff = (size_t)(b0 + r) * Hh + kb;
            *(uint4*)&As_hi[r * AST + pos * 8] = ((const uint4*)(hhi_in + goff))[pos];
            *(uint4*)&As_lo[r * AST + pos * 8] = ((const uint4*)(hlo_in + goff))[pos];
        }
        // stage B: 96 rows (3 gates x 32 j) x 64 k
#pragma unroll
        for (int i = 0; i < 3; ++i) {
            int q = tid + 256 * i;
            int p = q >> 3, pos = q & 7;
            int grow = ((p >> 5) << 9) + j0 + (p & 31);
            size_t goff = (size_t)grow * Hh + kb;
            *(uint4*)&Bs_hi[p * BST + pos * 8] = ((const uint4*)(g_Whi + goff))[pos];
            *(uint4*)&Bs_lo[p * BST + pos * 8] = ((const uint4*)(g_Wlo + goff))[pos];
        }
        __syncthreads();

#pragma unroll
        for (int kt = 0; kt < 4; ++kt) {
            const int aoff = kt * 16 + qcol * 4;
            uint2 ah0 = *(const uint2*)&As_hi[ar0 * AST + aoff];
            uint2 ah8 = *(const uint2*)&As_hi[ar8 * AST + aoff];
            uint2 al0 = *(const uint2*)&As_lo[ar0 * AST + aoff];
            uint2 al8 = *(const uint2*)&As_lo[ar8 * AST + aoff];
#pragma unroll
            for (int g = 0; g < 3; ++g)
#pragma unroll
                for (int nt = 0; nt < 2; ++nt) {
                    int brow = g * 32 + jp * 16 + nt * 8 + qrow;
                    uint2 bh = *(const uint2*)&Bs_hi[brow * BST + aoff];
                    uint2 bl = *(const uint2*)&Bs_lo[brow * BST + aoff];
                    float* c = acc[g][nt];
                    mma_bf16(c, ah0.x, ah8.x, ah0.y, ah8.y, bh.x, bh.y);
                    mma_bf16(c, ah0.x, ah8.x, ah0.y, ah8.y, bl.x, bl.y);
                    mma_bf16(c, al0.x, al8.x, al0.y, al8.y, bh.x, bh.y);
                }
        }
    }

    // -------- epilogue: gates fused in registers --------
    const float* xg_t = g_xg + (size_t)t * Bx * G3;
    const float* hf_in = g_h[t & 1];
    float* hf_out = g_h[(t + 1) & 1];
    __nv_bfloat16* hhi_out = g_hhi[(t + 1) & 1];
    __nv_bfloat16* hlo_out = g_hlo[(t + 1) & 1];

#pragma unroll
    for (int nt = 0; nt < 2; ++nt)
#pragma unroll
        for (int e = 0; e < 4; ++e) {
            int row = b0 + mt * 16 + qrow + ((e >> 1) ? 8 : 0);
            int j   = j0 + jp * 16 + nt * 8 + qcol * 2 + (e & 1);
            float hr = acc[0][nt][e];
            float hz = acc[1][nt][e];
            float hn = acc[2][nt][e] + bhh[2 * Hh + j];  // b_hh_n inside r*hn
            const float* xp = xg_t + (size_t)row * G3 + j;
            float r = 1.0f / (1.0f + expf(-(xp[0] + hr)));
            float z = 1.0f / (1.0f + expf(-(xp[Hh] + hz)));
            float n = tanhf(xp[2 * Hh] + r * hn);
            float hprev = hf_in[row * Hh + j];
            float hnew = (1.0f - z) * n + z * hprev;
            hf_out[row * Hh + j] = hnew;
            __nv_bfloat16 hi = __float2bfloat16(hnew);
            float lo = hnew - __bfloat162float(hi);
            int jj = (j & ~15) + kperm(j & 15);
            hhi_out[row * Hh + jj] = hi;
            hlo_out[row * Hh + jj] = __float2bfloat16(lo);
        }
}

// ---------------- kernel 3: out[b] = h_T[b,:] @ W_lin + b_lin -------------------
__global__ void out_kernel(const float* __restrict__ Wlin,
                           const float* __restrict__ blin,
                           float* __restrict__ out)
{
    int w = (blockIdx.x * blockDim.x + threadIdx.x) >> 5;
    int lane = threadIdx.x & 31;
    if (w >= Bx) return;
    const float* h = g_h[0] + (size_t)w * Hh;   // T=256 even -> final in buf 0
    float s = 0.0f;
#pragma unroll
    for (int i = 0; i < Hh / 32; ++i) s += h[lane + 32 * i] * Wlin[lane + 32 * i];
#pragma unroll
    for (int o = 16; o; o >>= 1) s += __shfl_xor_sync(0xffffffffu, s, o);
    if (lane == 0) out[w] = s + blin[0];
}

// ---------------- launch ---------------------------------------------------------
extern "C" void kernel_launch(void* const* d_in, const int* in_sizes, int n_in,
                              void* d_out, int out_size)
{
    const float* x    = (const float*)d_in[0];
    const float* Wih  = (const float*)d_in[1];
    const float* Whh  = (const float*)d_in[2];
    const float* bih  = (const float*)d_in[3];
    const float* bhh  = (const float*)d_in[4];
    const float* Wlin = (const float*)d_in[5];
    const float* blin = (const float*)d_in[6];
    float* out = (float*)d_out;

    cudaFuncSetAttribute(gru_step_kernel,
                         cudaFuncAttributeMaxDynamicSharedMemorySize, SMEM_BYTES);

    init_kernel<<<(Bx * Hh + 255) / 256, 256>>>();
    wconv_kernel<<<(G3 * Hh + 255) / 256, 256>>>(Whh);
    dim3 gx((Bx * Tt) / 64, G3 / 64);
    xg_kernel<<<gx, 256>>>(x, Wih, bih, bhh);
    for (int t = 0; t < Tt; ++t)
        gru_step_kernel<<<128, 256, SMEM_BYTES>>>(t, bhh);
    out_kernel<<<(Bx * 32) / 256, 256>>>(Wlin, blin, out);
}

// round 6
// speedup vs baseline: 2.1999x; 1.3749x over previous
#include <cuda_runtime.h>
#include <cuda_bf16.h>
#include <math.h>
#include <stdint.h>

#define Bx 512
#define Tt 256
#define Ii 128
#define Hh 512
#define G3 1536

// ---------------- scratch (device globals; no allocation allowed) ----------------
__device__ float g_xg[(size_t)Tt * (size_t)Bx * (size_t)G3]; // [T][B][3H] fp32
__device__ float g_h[2][Bx * Hh];                            // fp32 hidden, ping-pong
__device__ __nv_bfloat16 g_hhi[2][Bx * Hh];                  // h split-bf16 hi (perm-k)
__device__ __nv_bfloat16 g_hlo[2][Bx * Hh];                  // h split-bf16 lo (perm-k)
__device__ __nv_bfloat16 g_Whi[(size_t)G3 * Hh];             // W_hh bf16 hi (perm-k)
__device__ __nv_bfloat16 g_Wlo[(size_t)G3 * Hh];             // W_hh bf16 lo (perm-k)

// permutation within each 16-k block so mma fragment (k, k+1, k+8, k+9) is one LDS.64
__device__ __forceinline__ int kperm(int k) {
    return ((k & 7) >> 1) * 4 + (k & 1) + (((k >> 3) & 1) << 1);
}

// ---------------- init: zero h0 (fp32 + bf16 hi/lo), every launch ---------------
__global__ void init_kernel() {
    int i = blockIdx.x * 256 + threadIdx.x;
    if (i < Bx * Hh) {
        g_h[0][i] = 0.0f;
        g_hhi[0][i] = __float2bfloat16(0.0f);
        g_hlo[0][i] = __float2bfloat16(0.0f);
    }
}

// ---------------- W_hh -> split bf16, permuted-k layout (once per launch) --------
__global__ void wconv_kernel(const float* __restrict__ Whh) {
    int idx = blockIdx.x * 256 + threadIdx.x;
    if (idx >= G3 * Hh) return;
    int row = idx >> 9, k = idx & 511;
    float w = Whh[idx];
    __nv_bfloat16 hi = __float2bfloat16(w);
    float lo = w - __bfloat162float(hi);
    int kk = (k & ~15) + kperm(k & 15);
    g_Whi[(size_t)row * Hh + kk] = hi;
    g_Wlo[(size_t)row * Hh + kk] = __float2bfloat16(lo);
}

// ---------------- kernel 1: xg[t][b][g] = x[b,t,:] @ W_ih[g,:] + bias ------------
// bias = b_ih + b_hh for r/z gates; b_ih only for n gate (b_hh_n sits inside r*hn).
__global__ __launch_bounds__(256) void xg_kernel(
    const float* __restrict__ x, const float* __restrict__ Wih,
    const float* __restrict__ bih, const float* __restrict__ bhh)
{
    __shared__ float As[64][68];
    __shared__ float Bs[64][68];
    const int bt0 = blockIdx.x * 64;
    const int n0  = blockIdx.y * 64;
    const int tid = threadIdx.x;
    const int tx = tid & 15, ty = tid >> 4;

    float acc[4][4];
#pragma unroll
    for (int i = 0; i < 4; ++i)
#pragma unroll
        for (int j = 0; j < 4; ++j) acc[i][j] = 0.0f;

    for (int kc = 0; kc < 2; ++kc) {
        const int kb = kc * 64;
#pragma unroll
        for (int i = 0; i < 4; ++i) {
            int q = tid + 256 * i;
            int r = q >> 4, c4 = q & 15;
            float4 v = *(const float4*)(x + (size_t)(bt0 + r) * Ii + kb + c4 * 4);
            As[c4 * 4 + 0][r] = v.x; As[c4 * 4 + 1][r] = v.y;
            As[c4 * 4 + 2][r] = v.z; As[c4 * 4 + 3][r] = v.w;
        }
#pragma unroll
        for (int i = 0; i < 4; ++i) {
            int q = tid + 256 * i;
            int r = q >> 4, c4 = q & 15;
            float4 v = *(const float4*)(Wih + (size_t)(n0 + r) * Ii + kb + c4 * 4);
            Bs[c4 * 4 + 0][r] = v.x; Bs[c4 * 4 + 1][r] = v.y;
            Bs[c4 * 4 + 2][r] = v.z; Bs[c4 * 4 + 3][r] = v.w;
        }
        __syncthreads();
#pragma unroll 16
        for (int k = 0; k < 64; ++k) {
            float4 a4 = *(const float4*)&As[k][ty * 4];
            float4 b4 = *(const float4*)&Bs[k][tx * 4];
            float av[4] = {a4.x, a4.y, a4.z, a4.w};
            float bv[4] = {b4.x, b4.y, b4.z, b4.w};
#pragma unroll
            for (int i = 0; i < 4; ++i)
#pragma unroll
                for (int j = 0; j < 4; ++j) acc[i][j] += av[i] * bv[j];
        }
        __syncthreads();
    }

#pragma unroll
    for (int i = 0; i < 4; ++i) {
        int bt = bt0 + ty * 4 + i;
        int b = bt / Tt, t = bt % Tt;       // x rows are [B][T]
        float* dst = g_xg + ((size_t)t * Bx + b) * G3 + n0 + tx * 4;
#pragma unroll
        for (int j = 0; j < 4; ++j) {
            int g = n0 + tx * 4 + j;
            float bias = bih[g] + (g < 2 * Hh ? bhh[g] : 0.0f);
            dst[j] = acc[i][j] + bias;
        }
    }
}

// ---------------- bf16 mma.sync helper ------------------------------------------
__device__ __forceinline__ void mma_bf16(float* c,
    uint32_t a0, uint32_t a1, uint32_t a2, uint32_t a3,
    uint32_t b0, uint32_t b1)
{
    asm volatile(
        "mma.sync.aligned.m16n8k16.row.col.f32.bf16.bf16.f32 "
        "{%0,%1,%2,%3},{%4,%5,%6,%7},{%8,%9},{%0,%1,%2,%3};"
        : "+f"(c[0]), "+f"(c[1]), "+f"(c[2]), "+f"(c[3])
        : "r"(a0), "r"(a1), "r"(a2), "r"(a3), "r"(b0), "r"(b1));
}

// smem row strides (bf16 units): 80 -> 160B rows, conflict-free LDS.64 fragments
#define AST 80
#define BST 80
// per-stage partition (bf16 units)
#define OFF_AHI 0
#define OFF_ALO (64 * AST)
#define OFF_BHI (2 * 64 * AST)
#define OFF_BLO (2 * 64 * AST + 96 * BST)
#define STAGE_ELEMS (2 * 64 * AST + 2 * 96 * BST)       // 25600 bf16 = 51200 B
#define SMEM_BYTES (2 * STAGE_ELEMS * 2)                // 2 stages = 102400 B

// ---------------- kernel 2: one GRU timestep (tensor-core, split-bf16) -----------
// Double-buffered LDG->reg->STS pipeline, ONE sync per chunk:
//   iter ch: STS(chunk ch+1 from regs) | LDG(chunk ch+2 into regs) | MMA(chunk ch)
// Epilogue operands (xg, h_prev, b_hh_n) prefetched into registers at kernel
// start so their DRAM latency overlaps the whole GEMM.
__global__ __launch_bounds__(256) void gru_step_kernel(
    int t, const float* __restrict__ bhh)
{
    extern __shared__ __nv_bfloat16 sm[];

    const int tid  = threadIdx.x;
    const int lane = tid & 31;
    const int w    = tid >> 5;          // 8 warps
    const int mt   = w >> 1;            // 4 m-tiles of 16 batch rows
    const int jp   = w & 1;             // 2 j-halves of 16 cols
    const int qrow = lane >> 2;         // 0..7
    const int qcol = lane & 3;          // 0..3

    const int btile = blockIdx.x >> 4, jtile = blockIdx.x & 15;
    const int b0 = btile * 64, j0 = jtile * 32;

    const __nv_bfloat16* hhi_in = g_hhi[t & 1];
    const __nv_bfloat16* hlo_in = g_hlo[t & 1];

    // staging decomposition (same for every chunk)
    const int sr  = tid >> 3;           // 0..31 (row group; +32/+64 offsets)
    const int pos = tid & 7;            // 16B slot within 128B row

    uint4 ra_hi[2], ra_lo[2], rb_hi[3], rb_lo[3];   // in-flight chunk registers

    auto load_regs = [&](int ch) {
        const int kb = ch * 64;
#pragma unroll
        for (int i = 0; i < 2; ++i) {
            int r = sr + 32 * i;
            size_t goff = (size_t)(b0 + r) * Hh + kb + pos * 8;
            ra_hi[i] = *(const uint4*)(hhi_in + goff);
            ra_lo[i] = *(const uint4*)(hlo_in + goff);
        }
#pragma unroll
        for (int i = 0; i < 3; ++i) {
            int p = sr + 32 * i;
            int grow = ((p >> 5) << 9) + j0 + (p & 31);
            size_t goff = (size_t)grow * Hh + kb + pos * 8;
            rb_hi[i] = *(const uint4*)(g_Whi + goff);
            rb_lo[i] = *(const uint4*)(g_Wlo + goff);
        }
    };
    auto sts_regs = [&](int s) {
        __nv_bfloat16* st = sm + s * STAGE_ELEMS;
#pragma unroll
        for (int i = 0; i < 2; ++i) {
            int r = sr + 32 * i;
            *(uint4*)&st[OFF_AHI + r * AST + pos * 8] = ra_hi[i];
            *(uint4*)&st[OFF_ALO + r * AST + pos * 8] = ra_lo[i];
        }
#pragma unroll
        for (int i = 0; i < 3; ++i) {
            int p = sr + 32 * i;
            *(uint4*)&st[OFF_BHI + p * BST + pos * 8] = rb_hi[i];
            *(uint4*)&st[OFF_BLO + p * BST + pos * 8] = rb_lo[i];
        }
    };

    // prologue: chunk0 -> stage0; chunk1 in registers
    load_regs(0);
    sts_regs(0);
    load_regs(1);

    // -------- epilogue operand prefetch (overlaps the whole GEMM) --------
    const float* xg_t = g_xg + (size_t)t * Bx * G3;
    const float* hf_in = g_h[t & 1];
    float pre_xr[2][4], pre_xz[2][4], pre_xn[2][4], pre_h[2][4], pre_bn[2][4];
#pragma unroll
    for (int nt = 0; nt < 2; ++nt)
#pragma unroll
        for (int e = 0; e < 4; ++e) {
            int row = b0 + mt * 16 + qrow + ((e >> 1) ? 8 : 0);
            int j   = j0 + jp * 16 + nt * 8 + qcol * 2 + (e & 1);
            const float* xp = xg_t + (size_t)row * G3 + j;
            pre_xr[nt][e] = xp[0];
            pre_xz[nt][e] = xp[Hh];
            pre_xn[nt][e] = xp[2 * Hh];
            pre_h[nt][e]  = hf_in[row * Hh + j];
            pre_bn[nt][e] = bhh[2 * Hh + j];
        }
    __syncthreads();   // stage0 published

    float acc[3][2][4];                 // [gate][n-tile][c-regs]
#pragma unroll
    for (int g = 0; g < 3; ++g)
#pragma unroll
        for (int nt = 0; nt < 2; ++nt)
#pragma unroll
            for (int e = 0; e < 4; ++e) acc[g][nt][e] = 0.0f;

    const int ar0 = mt * 16 + qrow;
    const int ar8 = ar0 + 8;

#pragma unroll 1
    for (int ch = 0; ch < 8; ++ch) {
        // STS chunk ch+1 (regs) into the buffer consumed at ch-1; safe: one
        // barrier separates its last read (mma ch-1) from this write.
        if (ch < 7) sts_regs((ch + 1) & 1);
        if (ch < 6) load_regs(ch + 2);      // LDG issue; consumed next iter

        const __nv_bfloat16* st = sm + (ch & 1) * STAGE_ELEMS;
        const __nv_bfloat16* As_hi = st + OFF_AHI;
        const __nv_bfloat16* As_lo = st + OFF_ALO;
        const __nv_bfloat16* Bs_hi = st + OFF_BHI;
        const __nv_bfloat16* Bs_lo = st + OFF_BLO;

#pragma unroll
        for (int kt = 0; kt < 4; ++kt) {
            const int aoff = kt * 16 + qcol * 4;
            uint2 ah0 = *(const uint2*)&As_hi[ar0 * AST + aoff];
            uint2 ah8 = *(const uint2*)&As_hi[ar8 * AST + aoff];
            uint2 al0 = *(const uint2*)&As_lo[ar0 * AST + aoff];
            uint2 al8 = *(const uint2*)&As_lo[ar8 * AST + aoff];
#pragma unroll
            for (int g = 0; g < 3; ++g)
#pragma unroll
                for (int nt = 0; nt < 2; ++nt) {
                    int brow = g * 32 + jp * 16 + nt * 8 + qrow;
                    uint2 bh = *(const uint2*)&Bs_hi[brow * BST + aoff];
                    uint2 bl = *(const uint2*)&Bs_lo[brow * BST + aoff];
                    float* c = acc[g][nt];
                    mma_bf16(c, ah0.x, ah8.x, ah0.y, ah8.y, bh.x, bh.y);
                    mma_bf16(c, ah0.x, ah8.x, ah0.y, ah8.y, bl.x, bl.y);
                    mma_bf16(c, al0.x, al8.x, al0.y, al8.y, bh.x, bh.y);
                }
        }
        if (ch < 7) __syncthreads();    // publish stage (ch+1)&1, fence reads
    }

    // -------- epilogue: gates fused in registers --------
    float* hf_out = g_h[(t + 1) & 1];
    __nv_bfloat16* hhi_out = g_hhi[(t + 1) & 1];
    __nv_bfloat16* hlo_out = g_hlo[(t + 1) & 1];

#pragma unroll
    for (int nt = 0; nt < 2; ++nt)
#pragma unroll
        for (int e = 0; e < 4; ++e) {
            int row = b0 + mt * 16 + qrow + ((e >> 1) ? 8 : 0);
            int j   = j0 + jp * 16 + nt * 8 + qcol * 2 + (e & 1);
            float hr = acc[0][nt][e];
            float hz = acc[1][nt][e];
            float hn = acc[2][nt][e] + pre_bn[nt][e];   // b_hh_n inside r*hn
            float r = 1.0f / (1.0f + expf(-(pre_xr[nt][e] + hr)));
            float z = 1.0f / (1.0f + expf(-(pre_xz[nt][e] + hz)));
            float n = tanhf(pre_xn[nt][e] + r * hn);
            float hnew = (1.0f - z) * n + z * pre_h[nt][e];
            hf_out[row * Hh + j] = hnew;
            __nv_bfloat16 hi = __float2bfloat16(hnew);
            float lo = hnew - __bfloat162float(hi);
            int jj = (j & ~15) + kperm(j & 15);
            hhi_out[row * Hh + jj] = hi;
            hlo_out[row * Hh + jj] = __float2bfloat16(lo);
        }
}

// ---------------- kernel 3: out[b] = h_T[b,:] @ W_lin + b_lin -------------------
__global__ void out_kernel(const float* __restrict__ Wlin,
                           const float* __restrict__ blin,
                           float* __restrict__ out)
{
    int w = (blockIdx.x * blockDim.x + threadIdx.x) >> 5;
    int lane = threadIdx.x & 31;
    if (w >= Bx) return;
    const float* h = g_h[0] + (size_t)w * Hh;   // T=256 even -> final in buf 0
    float s = 0.0f;
#pragma unroll
    for (int i = 0; i < Hh / 32; ++i) s += h[lane + 32 * i] * Wlin[lane + 32 * i];
#pragma unroll
    for (int o = 16; o; o >>= 1) s += __shfl_xor_sync(0xffffffffu, s, o);
    if (lane == 0) out[w] = s + blin[0];
}

// ---------------- launch ---------------------------------------------------------
extern "C" void kernel_launch(void* const* d_in, const int* in_sizes, int n_in,
                              void* d_out, int out_size)
{
    const float* x    = (const float*)d_in[0];
    const float* Wih  = (const float*)d_in[1];
    const float* Whh  = (const float*)d_in[2];
    const float* bih  = (const float*)d_in[3];
    const float* bhh  = (const float*)d_in[4];
    const float* Wlin = (const float*)d_in[5];
    const float* blin = (const float*)d_in[6];
    float* out = (float*)d_out;

    cudaFuncSetAttribute(gru_step_kernel,
                         cudaFuncAttributeMaxDynamicSharedMemorySize, SMEM_BYTES);

    init_kernel<<<(Bx * Hh + 255) / 256, 256>>>();
    wconv_kernel<<<(G3 * Hh + 255) / 256, 256>>>(Whh);
    dim3 gx((Bx * Tt) / 64, G3 / 64);
    xg_kernel<<<gx, 256>>>(x, Wih, bih, bhh);
    for (int t = 0; t < Tt; ++t)
        gru_step_kernel<<<128, 256, SMEM_BYTES>>>(t, bhh);
    out_kernel<<<(Bx * 32) / 256, 256>>>(Wlin, blin, out);
}